// round 1
// baseline (speedup 1.0000x reference)
#include <cuda_runtime.h>
#include <math.h>

#define N_ 8
#define L_ 1024
#define H_ 16
#define D_ 64
#define E_ 1024
#define P_ 65   // smem pitch (floats) — odd pitch keeps strided column reads <=2-way conflicts

// Scratch (static device globals: allocation-free per harness rules)
__device__ float g_q[N_*H_*L_*D_];
__device__ float g_k[N_*H_*L_*D_];
__device__ float g_v[N_*H_*L_*D_];
__device__ float g_attn[N_*L_*H_*D_];

// ---------------------------------------------------------------------------
// Kernel 1: QKV projection. z = x viewed as (N*L*H, D) row-major.
// q/k/v stored [n,h,l,d] for attention-kernel locality.
// ---------------------------------------------------------------------------
__global__ void __launch_bounds__(256, 1)
sa_qkv_kernel(const float* __restrict__ x,
              const float* __restrict__ Wq, const float* __restrict__ bq,
              const float* __restrict__ Wk, const float* __restrict__ bk,
              const float* __restrict__ Wv, const float* __restrict__ bv)
{
    __shared__ float zs[64 * P_];
    __shared__ float ws[64 * P_];

    const int t  = threadIdx.x;
    const int tx = t & 15, ty = t >> 4;
    const int r0 = ty * 4, c0 = tx * 4;
    const int R0 = blockIdx.x * 64;

    // load z tile (64 x 64)
    for (int i = t; i < 64 * 16; i += 256) {
        int row = i >> 4, c = (i & 15) * 4;
        float4 v4 = *(const float4*)&x[(size_t)(R0 + row) * D_ + c];
        zs[row * P_ + c + 0] = v4.x; zs[row * P_ + c + 1] = v4.y;
        zs[row * P_ + c + 2] = v4.z; zs[row * P_ + c + 3] = v4.w;
    }

    // output row mapping: R = (n*L + l)*H + h  ->  row ((n*H+h)*L + l)
    size_t obase[4];
    #pragma unroll
    for (int r = 0; r < 4; r++) {
        int R = R0 + r0 + r;
        int n = R / (L_ * H_);
        int rem = R % (L_ * H_);
        int l = rem / H_;
        int h = rem % H_;
        obase[r] = ((size_t)((n * H_ + h) * L_ + l)) * D_;
    }

    const float* Ws[3] = {Wq, Wk, Wv};
    const float* Bs[3] = {bq, bk, bv};
    float*       Gs[3] = {g_q, g_k, g_v};

    #pragma unroll
    for (int m = 0; m < 3; m++) {
        __syncthreads();
        for (int i = t; i < 64 * 16; i += 256) {
            int row = i >> 4, c = (i & 15) * 4;
            float4 v4 = *(const float4*)&Ws[m][row * D_ + c];
            ws[row * P_ + c + 0] = v4.x; ws[row * P_ + c + 1] = v4.y;
            ws[row * P_ + c + 2] = v4.z; ws[row * P_ + c + 3] = v4.w;
        }
        __syncthreads();

        float acc[4][4] = {};
        #pragma unroll 8
        for (int d = 0; d < 64; d++) {
            float zv[4], wv[4];
            #pragma unroll
            for (int r = 0; r < 4; r++) zv[r] = zs[(r0 + r) * P_ + d];
            #pragma unroll
            for (int c = 0; c < 4; c++) wv[c] = ws[(c0 + c) * P_ + d];
            #pragma unroll
            for (int r = 0; r < 4; r++)
                #pragma unroll
                for (int c = 0; c < 4; c++)
                    acc[r][c] += zv[r] * wv[c];
        }

        #pragma unroll
        for (int r = 0; r < 4; r++)
            #pragma unroll
            for (int c = 0; c < 4; c++)
                Gs[m][obase[r] + c0 + c] = acc[r][c] + Bs[m][c0 + c];
    }
}

// ---------------------------------------------------------------------------
// Kernel 2: fused attention per (n, h, 64-row q tile).
// out_tile = softmax(qk/32) @ V  +  S @ V
// S[i,j] = (j<=i) ? q_i . Erel[L-1-i+j] : 0   (skew+mask closed form)
// ---------------------------------------------------------------------------
__global__ void __launch_bounds__(256, 1)
sa_attn_kernel(const float* __restrict__ Erel)
{
    extern __shared__ float sm[];
    float* q_s = sm;                 // 64 x P_
    float* k_s = q_s + 64 * P_;      // 64 x P_
    float* v_s = k_s + 64 * P_;      // 64 x P_
    float* p_s = v_s + 64 * P_;      // 64 x P_  (softmax weights)
    float* b_s = p_s + 64 * P_;      // 64 x P_  (bias weights)
    float* e_s = b_s + 64 * P_;      // 128 x P_ (Erel band)

    const int qt = blockIdx.x;
    const int h  = blockIdx.y;
    const int n  = blockIdx.z;
    const int q0 = qt * 64;

    const size_t hb = ((size_t)(n * H_ + h)) * L_ * D_;
    const float* qp = g_q + hb;
    const float* kp = g_k + hb;
    const float* vp = g_v + hb;

    const int t  = threadIdx.x;
    const int tx = t & 15, ty = t >> 4;
    const int r0 = ty * 4, c0 = tx * 4;

    for (int i = t; i < 64 * 16; i += 256) {
        int row = i >> 4, c = (i & 15) * 4;
        float4 v4 = *(const float4*)&qp[(size_t)(q0 + row) * D_ + c];
        q_s[row * P_ + c + 0] = v4.x; q_s[row * P_ + c + 1] = v4.y;
        q_s[row * P_ + c + 2] = v4.z; q_s[row * P_ + c + 3] = v4.w;
    }

    float accS[4][4] = {};
    float accB[4][4] = {};
    float mrow[4] = {-INFINITY, -INFINITY, -INFINITY, -INFINITY};
    float srow[4] = {0.f, 0.f, 0.f, 0.f};
    const float scale = 0.03125f;   // 1/sqrt(1024)

    for (int kt = 0; kt < 16; kt++) {
        const int k0 = kt * 64;
        const bool hasb = (kt <= qt);

        __syncthreads();   // protect k_s/v_s/e_s/p_s/b_s from previous tile readers
        for (int i = t; i < 64 * 16; i += 256) {
            int row = i >> 4, c = (i & 15) * 4;
            float4 kv4 = *(const float4*)&kp[(size_t)(k0 + row) * D_ + c];
            float4 vv4 = *(const float4*)&vp[(size_t)(k0 + row) * D_ + c];
            k_s[row * P_ + c + 0] = kv4.x; k_s[row * P_ + c + 1] = kv4.y;
            k_s[row * P_ + c + 2] = kv4.z; k_s[row * P_ + c + 3] = kv4.w;
            v_s[row * P_ + c + 0] = vv4.x; v_s[row * P_ + c + 1] = vv4.y;
            v_s[row * P_ + c + 2] = vv4.z; v_s[row * P_ + c + 3] = vv4.w;
        }
        if (hasb) {
            const int rb = L_ - 64 - q0 + k0;   // >= 0 always
            for (int i = t; i < 128 * 16; i += 256) {
                int row = i >> 4, c = (i & 15) * 4;
                int rr = rb + row;
                float4 e4 = (rr < L_) ? *(const float4*)&Erel[(size_t)rr * D_ + c]
                                      : make_float4(0.f, 0.f, 0.f, 0.f);
                e_s[row * P_ + c + 0] = e4.x; e_s[row * P_ + c + 1] = e4.y;
                e_s[row * P_ + c + 2] = e4.z; e_s[row * P_ + c + 3] = e4.w;
            }
        }
        __syncthreads();

        // ---- qk scores (4x4 per thread) ----
        float s[4][4] = {};
        #pragma unroll 8
        for (int d = 0; d < 64; d++) {
            float qv[4], kv[4];
            #pragma unroll
            for (int r = 0; r < 4; r++) qv[r] = q_s[(r0 + r) * P_ + d];
            #pragma unroll
            for (int c = 0; c < 4; c++) kv[c] = k_s[(c0 + c) * P_ + d];
            #pragma unroll
            for (int r = 0; r < 4; r++)
                #pragma unroll
                for (int c = 0; c < 4; c++)
                    s[r][c] += qv[r] * kv[c];
        }

        // ---- online softmax update (rows grouped over 16 lanes) ----
        #pragma unroll
        for (int r = 0; r < 4; r++) {
            float mt = -INFINITY;
            #pragma unroll
            for (int c = 0; c < 4; c++) { s[r][c] *= scale; mt = fmaxf(mt, s[r][c]); }
            mt = fmaxf(mt, __shfl_xor_sync(0xffffffffu, mt, 8));
            mt = fmaxf(mt, __shfl_xor_sync(0xffffffffu, mt, 4));
            mt = fmaxf(mt, __shfl_xor_sync(0xffffffffu, mt, 2));
            mt = fmaxf(mt, __shfl_xor_sync(0xffffffffu, mt, 1));
            float mn = fmaxf(mrow[r], mt);
            float f  = __expf(mrow[r] - mn);
            mrow[r]  = mn;
            float rs = 0.f;
            #pragma unroll
            for (int c = 0; c < 4; c++) {
                float p = __expf(s[r][c] - mn);
                p_s[(r0 + r) * P_ + c0 + c] = p;
                rs += p;
            }
            rs += __shfl_xor_sync(0xffffffffu, rs, 8);
            rs += __shfl_xor_sync(0xffffffffu, rs, 4);
            rs += __shfl_xor_sync(0xffffffffu, rs, 2);
            rs += __shfl_xor_sync(0xffffffffu, rs, 1);
            srow[r] = srow[r] * f + rs;
            #pragma unroll
            for (int c = 0; c < 4; c++) accS[r][c] *= f;
        }

        // ---- relative-bias scores: b[i,j] = q_i . Erel[L-1-i+j], local row 63-ti+tj ----
        if (hasb) {
            float b[4][4] = {};
            #pragma unroll 4
            for (int d = 0; d < 64; d++) {
                float qv[4];
                #pragma unroll
                for (int r = 0; r < 4; r++) qv[r] = q_s[(r0 + r) * P_ + d];
                #pragma unroll
                for (int r = 0; r < 4; r++) {
                    #pragma unroll
                    for (int c = 0; c < 4; c++) {
                        int er = 63 - (r0 + r) + (c0 + c);
                        b[r][c] += qv[r] * e_s[er * P_ + d];
                    }
                }
            }
            #pragma unroll
            for (int r = 0; r < 4; r++)
                #pragma unroll
                for (int c = 0; c < 4; c++) {
                    bool ok = (k0 + c0 + c) <= (q0 + r0 + r);
                    b_s[(r0 + r) * P_ + c0 + c] = ok ? b[r][c] : 0.f;
                }
        }
        __syncthreads();

        // ---- accumulate (P @ V) and (B @ V) ----
        if (hasb) {
            #pragma unroll 4
            for (int j = 0; j < 64; j++) {
                float vv[4];
                #pragma unroll
                for (int c = 0; c < 4; c++) vv[c] = v_s[j * P_ + c0 + c];
                #pragma unroll
                for (int r = 0; r < 4; r++) {
                    float pw = p_s[(r0 + r) * P_ + j];
                    float bw = b_s[(r0 + r) * P_ + j];
                    #pragma unroll
                    for (int c = 0; c < 4; c++) {
                        accS[r][c] += pw * vv[c];
                        accB[r][c] += bw * vv[c];
                    }
                }
            }
        } else {
            #pragma unroll 4
            for (int j = 0; j < 64; j++) {
                float vv[4];
                #pragma unroll
                for (int c = 0; c < 4; c++) vv[c] = v_s[j * P_ + c0 + c];
                #pragma unroll
                for (int r = 0; r < 4; r++) {
                    float pw = p_s[(r0 + r) * P_ + j];
                    #pragma unroll
                    for (int c = 0; c < 4; c++)
                        accS[r][c] += pw * vv[c];
                }
            }
        }
    }

    // epilogue: out[n, q, h, d] = accS/srow + accB
    #pragma unroll
    for (int r = 0; r < 4; r++) {
        int i = q0 + r0 + r;
        float inv = 1.f / srow[r];
        float* op = g_attn + ((size_t)((n * L_ + i) * H_ + h)) * D_ + c0;
        #pragma unroll
        for (int c = 0; c < 4; c++)
            op[c] = accS[r][c] * inv + accB[r][c];
    }
}

// ---------------------------------------------------------------------------
// Kernel 3: output projection. out(8192,1024) = g_attn(8192,1024) @ Wo^T + bo
// ---------------------------------------------------------------------------
__global__ void __launch_bounds__(256, 1)
sa_outproj_kernel(const float* __restrict__ Wo, const float* __restrict__ bo,
                  float* __restrict__ out)
{
    __shared__ float a_s[64 * P_];
    __shared__ float w_s[64 * P_];

    const int e0 = blockIdx.x * 64;
    const int m0 = blockIdx.y * 64;
    const int t  = threadIdx.x;
    const int tx = t & 15, ty = t >> 4;
    const int r0 = ty * 4, c0 = tx * 4;

    float acc[4][4] = {};

    for (int kc = 0; kc < E_; kc += 64) {
        __syncthreads();
        for (int i = t; i < 64 * 16; i += 256) {
            int row = i >> 4, c = (i & 15) * 4;
            float4 a4 = *(const float4*)&g_attn[(size_t)(m0 + row) * E_ + kc + c];
            float4 w4 = *(const float4*)&Wo[(size_t)(e0 + row) * E_ + kc + c];
            a_s[row * P_ + c + 0] = a4.x; a_s[row * P_ + c + 1] = a4.y;
            a_s[row * P_ + c + 2] = a4.z; a_s[row * P_ + c + 3] = a4.w;
            w_s[row * P_ + c + 0] = w4.x; w_s[row * P_ + c + 1] = w4.y;
            w_s[row * P_ + c + 2] = w4.z; w_s[row * P_ + c + 3] = w4.w;
        }
        __syncthreads();

        #pragma unroll 8
        for (int d = 0; d < 64; d++) {
            float av[4], wv[4];
            #pragma unroll
            for (int r = 0; r < 4; r++) av[r] = a_s[(r0 + r) * P_ + d];
            #pragma unroll
            for (int c = 0; c < 4; c++) wv[c] = w_s[(c0 + c) * P_ + d];
            #pragma unroll
            for (int r = 0; r < 4; r++)
                #pragma unroll
                for (int c = 0; c < 4; c++)
                    acc[r][c] += av[r] * wv[c];
        }
    }

    #pragma unroll
    for (int r = 0; r < 4; r++)
        #pragma unroll
        for (int c = 0; c < 4; c++)
            out[(size_t)(m0 + r0 + r) * E_ + e0 + c0 + c] = acc[r][c] + bo[e0 + c0 + c];
}

// ---------------------------------------------------------------------------
extern "C" void kernel_launch(void* const* d_in, const int* in_sizes, int n_in,
                              void* d_out, int out_size)
{
    const float* x    = (const float*)d_in[0];
    const float* Wq   = (const float*)d_in[1];
    const float* bq   = (const float*)d_in[2];
    const float* Wk   = (const float*)d_in[3];
    const float* bk   = (const float*)d_in[4];
    const float* Wv   = (const float*)d_in[5];
    const float* bv   = (const float*)d_in[6];
    const float* Erel = (const float*)d_in[7];
    const float* Wo   = (const float*)d_in[8];
    const float* bo   = (const float*)d_in[9];
    float* out = (float*)d_out;

    const int attn_smem = 448 * P_ * (int)sizeof(float);   // 116,480 B
    cudaFuncSetAttribute(sa_attn_kernel,
                         cudaFuncAttributeMaxDynamicSharedMemorySize, attn_smem);

    sa_qkv_kernel<<<(N_ * L_ * H_) / 64, 256>>>(x, Wq, bq, Wk, bk, Wv, bv);
    sa_attn_kernel<<<dim3(L_ / 64, H_, N_), 256, attn_smem>>>(Erel);
    sa_outproj_kernel<<<dim3(E_ / 64, (N_ * L_) / 64), 256>>>(Wo, bo, out);
}

// round 2
// speedup vs baseline: 2.6824x; 2.6824x over previous
#include <cuda_runtime.h>
#include <math.h>

#define N_ 8
#define L_ 1024
#define H_ 16
#define D_ 64
#define E_ 1024
#define P_ 65    // scalar-kernel pitch
#define PW 68    // mma-kernel pitch: bank = (4*row + col) % 32 -> conflict-free frag loads
#define QT 128   // attention q-tile rows
#define KT 64    // attention k-tile rows

// Scratch (static device globals: allocation-free per harness rules)
__device__ float g_q[N_*H_*L_*D_];
__device__ float g_k[N_*H_*L_*D_];
__device__ float g_v[N_*H_*L_*D_];
__device__ float g_attn[N_*L_*H_*D_];

// ---------------------------------------------------------------------------
// mma.sync tf32 helpers
// ---------------------------------------------------------------------------
__device__ __forceinline__ unsigned f2tf(float f) {
    unsigned u;
    asm("cvt.rna.tf32.f32 %0, %1;" : "=r"(u) : "f"(f));
    return u;
}

__device__ __forceinline__ void mma_tf32(float c[4],
                                         unsigned a0, unsigned a1, unsigned a2, unsigned a3,
                                         unsigned b0, unsigned b1) {
    asm volatile(
        "mma.sync.aligned.m16n8k8.row.col.f32.tf32.tf32.f32 "
        "{%0,%1,%2,%3}, {%4,%5,%6,%7}, {%8,%9}, {%0,%1,%2,%3};"
        : "+f"(c[0]), "+f"(c[1]), "+f"(c[2]), "+f"(c[3])
        : "r"(a0), "r"(a1), "r"(a2), "r"(a3), "r"(b0), "r"(b1));
}

// ---------------------------------------------------------------------------
// Kernel 1: QKV projection (scalar fp32; memory-bound, keeps exact precision)
// ---------------------------------------------------------------------------
__global__ void __launch_bounds__(256, 1)
sa_qkv_kernel(const float* __restrict__ x,
              const float* __restrict__ Wq, const float* __restrict__ bq,
              const float* __restrict__ Wk, const float* __restrict__ bk,
              const float* __restrict__ Wv, const float* __restrict__ bv)
{
    __shared__ float zs[64 * P_];
    __shared__ float ws[64 * P_];

    const int t  = threadIdx.x;
    const int tx = t & 15, ty = t >> 4;
    const int r0 = ty * 4, c0 = tx * 4;
    const int R0 = blockIdx.x * 64;

    for (int i = t; i < 64 * 16; i += 256) {
        int row = i >> 4, c = (i & 15) * 4;
        float4 v4 = *(const float4*)&x[(size_t)(R0 + row) * D_ + c];
        zs[row * P_ + c + 0] = v4.x; zs[row * P_ + c + 1] = v4.y;
        zs[row * P_ + c + 2] = v4.z; zs[row * P_ + c + 3] = v4.w;
    }

    size_t obase[4];
    #pragma unroll
    for (int r = 0; r < 4; r++) {
        int R = R0 + r0 + r;
        int n = R / (L_ * H_);
        int rem = R % (L_ * H_);
        int l = rem / H_;
        int h = rem % H_;
        obase[r] = ((size_t)((n * H_ + h) * L_ + l)) * D_;
    }

    const float* Ws[3] = {Wq, Wk, Wv};
    const float* Bs[3] = {bq, bk, bv};
    float*       Gs[3] = {g_q, g_k, g_v};

    #pragma unroll
    for (int m = 0; m < 3; m++) {
        __syncthreads();
        for (int i = t; i < 64 * 16; i += 256) {
            int row = i >> 4, c = (i & 15) * 4;
            float4 v4 = *(const float4*)&Ws[m][row * D_ + c];
            ws[row * P_ + c + 0] = v4.x; ws[row * P_ + c + 1] = v4.y;
            ws[row * P_ + c + 2] = v4.z; ws[row * P_ + c + 3] = v4.w;
        }
        __syncthreads();

        float acc[4][4] = {};
        #pragma unroll 8
        for (int d = 0; d < 64; d++) {
            float zv[4], wv[4];
            #pragma unroll
            for (int r = 0; r < 4; r++) zv[r] = zs[(r0 + r) * P_ + d];
            #pragma unroll
            for (int c = 0; c < 4; c++) wv[c] = ws[(c0 + c) * P_ + d];
            #pragma unroll
            for (int r = 0; r < 4; r++)
                #pragma unroll
                for (int c = 0; c < 4; c++)
                    acc[r][c] += zv[r] * wv[c];
        }

        #pragma unroll
        for (int r = 0; r < 4; r++)
            #pragma unroll
            for (int c = 0; c < 4; c++)
                Gs[m][obase[r] + c0 + c] = acc[r][c] + Bs[m][c0 + c];
    }
}

// ---------------------------------------------------------------------------
// Kernel 2: fused attention, tf32 mma.sync.
// CTA = (q-tile of 128 rows, h, n); 8 warps, 16 q rows per warp.
// out = softmax(QK^T/32) @ V  +  B @ V,
//   B[i,j] = (j<=i) ? q_i . Erel[L-1-i+j] : 0.
// Bias scores via G = Q . Eband^T (per-warp 80-col window), scattered along
// the diagonal mapping j = c - 127 + r into b_s.
// ---------------------------------------------------------------------------
__global__ void __launch_bounds__(256, 1)
sa_attn_mma(const float* __restrict__ Erel)
{
    extern __shared__ float sm[];
    float* k_s = sm;                   // KT x PW (tf32)
    float* v_s = k_s + KT * PW;        // KT x PW (tf32)
    float* p_s = v_s + KT * PW;        // QT x PW (tf32, softmax weights)
    float* b_s = p_s + QT * PW;        // QT x PW (tf32, bias weights)
    float* e_s = b_s + QT * PW;        // 192 x PW (tf32, Erel band)
    float* q_s = e_s;                  // aliased: Q staging before main loop

    const int qt8 = blockIdx.x;
    const int h   = blockIdx.y;
    const int n   = blockIdx.z;
    const int q0  = qt8 * QT;

    const size_t hb = ((size_t)(n * H_ + h)) * L_ * D_;
    const float* qp = g_q + hb;
    const float* kp = g_k + hb;
    const float* vp = g_v + hb;

    const int t    = threadIdx.x;
    const int lane = t & 31;
    const int w    = t >> 5;
    const int grp  = lane >> 2;    // 0..7
    const int qd   = lane & 3;     // 0..3
    const int wr0  = w * 16;       // warp's first local q row

    // ---- stage Q tile, then build per-warp tf32 A fragments (held all kernel)
    for (int i = t; i < QT * 16; i += 256) {
        int row = i >> 4, c = (i & 15) * 4;
        float4 v4 = *(const float4*)&qp[(size_t)(q0 + row) * D_ + c];
        q_s[row * PW + c + 0] = v4.x; q_s[row * PW + c + 1] = v4.y;
        q_s[row * PW + c + 2] = v4.z; q_s[row * PW + c + 3] = v4.w;
    }
    __syncthreads();

    unsigned qa[8][4];
    {
        int rA = wr0 + grp, rB = rA + 8;
        #pragma unroll
        for (int ks = 0; ks < 8; ks++) {
            qa[ks][0] = f2tf(q_s[rA * PW + ks * 8 + qd]);
            qa[ks][1] = f2tf(q_s[rB * PW + ks * 8 + qd]);
            qa[ks][2] = f2tf(q_s[rA * PW + ks * 8 + qd + 4]);
            qa[ks][3] = f2tf(q_s[rB * PW + ks * 8 + qd + 4]);
        }
    }

    float accS[8][4] = {};
    float accB[8][4] = {};
    float m_lo = -INFINITY, m_hi = -INFINITY;
    float l_lo = 0.f, l_hi = 0.f;
    const float scale = 0.03125f;   // 1/sqrt(1024)

    const unsigned* ku = (const unsigned*)k_s;
    const unsigned* vu = (const unsigned*)v_s;
    const unsigned* pu = (const unsigned*)p_s;
    const unsigned* bu = (const unsigned*)b_s;
    const unsigned* eu = (const unsigned*)e_s;

    for (int kt = 0; kt < 16; kt++) {
        const int  k0   = kt * KT;
        const bool hasb = (k0 <= q0 + QT - 1);

        __syncthreads();   // all consumers of k_s/v_s/e_s done (also guards q_s aliasing)
        for (int i = t; i < KT * 16; i += 256) {
            int row = i >> 4, c = (i & 15) * 4;
            float4 kv = *(const float4*)&kp[(size_t)(k0 + row) * D_ + c];
            float4 vv = *(const float4*)&vp[(size_t)(k0 + row) * D_ + c];
            k_s[row * PW + c + 0] = __uint_as_float(f2tf(kv.x));
            k_s[row * PW + c + 1] = __uint_as_float(f2tf(kv.y));
            k_s[row * PW + c + 2] = __uint_as_float(f2tf(kv.z));
            k_s[row * PW + c + 3] = __uint_as_float(f2tf(kv.w));
            v_s[row * PW + c + 0] = __uint_as_float(f2tf(vv.x));
            v_s[row * PW + c + 1] = __uint_as_float(f2tf(vv.y));
            v_s[row * PW + c + 2] = __uint_as_float(f2tf(vv.z));
            v_s[row * PW + c + 3] = __uint_as_float(f2tf(vv.w));
        }
        if (hasb) {
            const int rb = L_ - QT - q0 + k0;   // >= 0 always
            for (int i = t; i < 192 * 16; i += 256) {
                int row = i >> 4, c = (i & 15) * 4;
                int rr = rb + row;
                float4 e4 = (rr < L_) ? *(const float4*)&Erel[(size_t)rr * D_ + c]
                                      : make_float4(0.f, 0.f, 0.f, 0.f);
                e_s[row * PW + c + 0] = __uint_as_float(f2tf(e4.x));
                e_s[row * PW + c + 1] = __uint_as_float(f2tf(e4.y));
                e_s[row * PW + c + 2] = __uint_as_float(f2tf(e4.z));
                e_s[row * PW + c + 3] = __uint_as_float(f2tf(e4.w));
            }
        }
        __syncthreads();

        // ---- S = Q K^T (per warp: 16 x 64) ----
        float sfr[8][4];
        #pragma unroll
        for (int nt = 0; nt < 8; nt++) {
            sfr[nt][0] = sfr[nt][1] = sfr[nt][2] = sfr[nt][3] = 0.f;
            #pragma unroll
            for (int ks = 0; ks < 8; ks++) {
                unsigned b0 = ku[(nt * 8 + grp) * PW + ks * 8 + qd];
                unsigned b1 = ku[(nt * 8 + grp) * PW + ks * 8 + qd + 4];
                mma_tf32(sfr[nt], qa[ks][0], qa[ks][1], qa[ks][2], qa[ks][3], b0, b1);
            }
        }

        // ---- online softmax (rows lane>>2 and lane>>2+8) ----
        float mt_lo = -INFINITY, mt_hi = -INFINITY;
        #pragma unroll
        for (int nt = 0; nt < 8; nt++) {
            #pragma unroll
            for (int r = 0; r < 4; r++) sfr[nt][r] *= scale;
            mt_lo = fmaxf(mt_lo, fmaxf(sfr[nt][0], sfr[nt][1]));
            mt_hi = fmaxf(mt_hi, fmaxf(sfr[nt][2], sfr[nt][3]));
        }
        mt_lo = fmaxf(mt_lo, __shfl_xor_sync(0xffffffffu, mt_lo, 1));
        mt_lo = fmaxf(mt_lo, __shfl_xor_sync(0xffffffffu, mt_lo, 2));
        mt_hi = fmaxf(mt_hi, __shfl_xor_sync(0xffffffffu, mt_hi, 1));
        mt_hi = fmaxf(mt_hi, __shfl_xor_sync(0xffffffffu, mt_hi, 2));

        float mn_lo = fmaxf(m_lo, mt_lo);
        float mn_hi = fmaxf(m_hi, mt_hi);
        float f_lo  = __expf(m_lo - mn_lo);
        float f_hi  = __expf(m_hi - mn_hi);
        m_lo = mn_lo; m_hi = mn_hi;

        float rs_lo = 0.f, rs_hi = 0.f;
        {
            int rA = wr0 + grp, rB = rA + 8;
            #pragma unroll
            for (int nt = 0; nt < 8; nt++) {
                float p0 = __expf(sfr[nt][0] - mn_lo);
                float p1 = __expf(sfr[nt][1] - mn_lo);
                float p2 = __expf(sfr[nt][2] - mn_hi);
                float p3 = __expf(sfr[nt][3] - mn_hi);
                rs_lo += p0 + p1;
                rs_hi += p2 + p3;
                float2 plo = make_float2(__uint_as_float(f2tf(p0)), __uint_as_float(f2tf(p1)));
                float2 phi = make_float2(__uint_as_float(f2tf(p2)), __uint_as_float(f2tf(p3)));
                *(float2*)&p_s[rA * PW + nt * 8 + 2 * qd] = plo;
                *(float2*)&p_s[rB * PW + nt * 8 + 2 * qd] = phi;
            }
        }
        rs_lo += __shfl_xor_sync(0xffffffffu, rs_lo, 1);
        rs_lo += __shfl_xor_sync(0xffffffffu, rs_lo, 2);
        rs_hi += __shfl_xor_sync(0xffffffffu, rs_hi, 1);
        rs_hi += __shfl_xor_sync(0xffffffffu, rs_hi, 2);
        l_lo = l_lo * f_lo + rs_lo;
        l_hi = l_hi * f_hi + rs_hi;
        #pragma unroll
        for (int nt = 0; nt < 8; nt++) {
            accS[nt][0] *= f_lo; accS[nt][1] *= f_lo;
            accS[nt][2] *= f_hi; accS[nt][3] *= f_hi;
        }

        // ---- bias scores: G = Q Eband^T, scatter diagonal j = c - 127 + r ----
        if (hasb) {
            if (k0 + KT - 1 > q0) {
                // partial-mask tile: pre-zero this warp's rows of b_s
                for (int i = lane; i < 16 * 16; i += 32) {
                    int row = wr0 + (i >> 4), c = (i & 15) * 4;
                    *(float4*)&b_s[row * PW + c] = make_float4(0.f, 0.f, 0.f, 0.f);
                }
            }
            const int nt_lo = (112 - wr0) >> 3;   // warp's diagonal window start
            int rA = wr0 + grp, rB = rA + 8;
            #pragma unroll
            for (int nn = 0; nn < 10; nn++) {
                int nt = nt_lo + nn;
                float g[4] = {0.f, 0.f, 0.f, 0.f};
                #pragma unroll
                for (int ks = 0; ks < 8; ks++) {
                    unsigned b0 = eu[(nt * 8 + grp) * PW + ks * 8 + qd];
                    unsigned b1 = eu[(nt * 8 + grp) * PW + ks * 8 + qd + 4];
                    mma_tf32(g, qa[ks][0], qa[ks][1], qa[ks][2], qa[ks][3], b0, b1);
                }
                int cc = nt * 8 + 2 * qd;
                #pragma unroll
                for (int e = 0; e < 4; e++) {
                    int r = (e >= 2) ? rB : rA;
                    int c = cc + (e & 1);
                    int j = c - (QT - 1) + r;
                    if (j >= 0 && j < KT && (k0 + j) <= (q0 + r))
                        b_s[r * PW + j] = __uint_as_float(f2tf(g[e]));
                }
            }
        }
        __syncwarp();   // p_s/b_s rows are warp-private; order STS -> LDS within warp

        // ---- accumulate P @ V (and B @ V) ----
        if (hasb) {
            int rA = wr0 + grp, rB = rA + 8;
            #pragma unroll
            for (int ks = 0; ks < 8; ks++) {
                unsigned pa0 = pu[rA * PW + ks * 8 + qd];
                unsigned pa1 = pu[rB * PW + ks * 8 + qd];
                unsigned pa2 = pu[rA * PW + ks * 8 + qd + 4];
                unsigned pa3 = pu[rB * PW + ks * 8 + qd + 4];
                unsigned ba0 = bu[rA * PW + ks * 8 + qd];
                unsigned ba1 = bu[rB * PW + ks * 8 + qd];
                unsigned ba2 = bu[rA * PW + ks * 8 + qd + 4];
                unsigned ba3 = bu[rB * PW + ks * 8 + qd + 4];
                #pragma unroll
                for (int nt = 0; nt < 8; nt++) {
                    unsigned vb0 = vu[(ks * 8 + qd) * PW + nt * 8 + grp];
                    unsigned vb1 = vu[(ks * 8 + qd + 4) * PW + nt * 8 + grp];
                    mma_tf32(accS[nt], pa0, pa1, pa2, pa3, vb0, vb1);
                    mma_tf32(accB[nt], ba0, ba1, ba2, ba3, vb0, vb1);
                }
            }
        } else {
            int rA = wr0 + grp, rB = rA + 8;
            #pragma unroll
            for (int ks = 0; ks < 8; ks++) {
                unsigned pa0 = pu[rA * PW + ks * 8 + qd];
                unsigned pa1 = pu[rB * PW + ks * 8 + qd];
                unsigned pa2 = pu[rA * PW + ks * 8 + qd + 4];
                unsigned pa3 = pu[rB * PW + ks * 8 + qd + 4];
                #pragma unroll
                for (int nt = 0; nt < 8; nt++) {
                    unsigned vb0 = vu[(ks * 8 + qd) * PW + nt * 8 + grp];
                    unsigned vb1 = vu[(ks * 8 + qd + 4) * PW + nt * 8 + grp];
                    mma_tf32(accS[nt], pa0, pa1, pa2, pa3, vb0, vb1);
                }
            }
        }
    }

    // ---- epilogue: out[n, q, h, d] = accS/l + accB ----
    {
        float inv_lo = 1.f / l_lo;
        float inv_hi = 1.f / l_hi;
        int iA = q0 + wr0 + grp;
        int iB = iA + 8;
        float* opA = g_attn + ((size_t)((n * L_ + iA) * H_ + h)) * D_;
        float* opB = g_attn + ((size_t)((n * L_ + iB) * H_ + h)) * D_;
        #pragma unroll
        for (int nt = 0; nt < 8; nt++) {
            int d = nt * 8 + 2 * qd;
            float2 olo = make_float2(accS[nt][0] * inv_lo + accB[nt][0],
                                     accS[nt][1] * inv_lo + accB[nt][1]);
            float2 ohi = make_float2(accS[nt][2] * inv_hi + accB[nt][2],
                                     accS[nt][3] * inv_hi + accB[nt][3]);
            *(float2*)&opA[d] = olo;
            *(float2*)&opB[d] = ohi;
        }
    }
}

// ---------------------------------------------------------------------------
// Kernel 3: output projection, tf32 mma.sync.
// out(8192,1024) = g_attn(8192,1024) @ Wo^T + bo
// CTA tile 128(M) x 128(N), k-chunks of 64; 8 warps as 2(m) x 4(n),
// warp tile 64 x 32 (4 m-tiles x 4 n-tiles of m16n8k8).
// ---------------------------------------------------------------------------
__global__ void __launch_bounds__(256, 1)
sa_outproj_mma(const float* __restrict__ Wo, const float* __restrict__ bo,
               float* __restrict__ out)
{
    extern __shared__ float sm[];
    float* a_s = sm;               // 128 x PW (tf32)
    float* w_s = sm + 128 * PW;    // 128 x PW (tf32)

    const int e0 = blockIdx.x * 128;
    const int m0 = blockIdx.y * 128;
    const int t    = threadIdx.x;
    const int lane = t & 31;
    const int w    = t >> 5;
    const int grp  = lane >> 2;
    const int qd   = lane & 3;
    const int wm   = (w >> 2) * 64;   // warp m offset (0 or 64)
    const int wn   = (w & 3) * 32;    // warp n offset (0,32,64,96)

    const unsigned* au = (const unsigned*)a_s;
    const unsigned* wu = (const unsigned*)w_s;

    float acc[4][4][4] = {};

    for (int kc = 0; kc < E_; kc += 64) {
        __syncthreads();
        for (int i = t; i < 128 * 16; i += 256) {
            int row = i >> 4, c = (i & 15) * 4;
            float4 a4 = *(const float4*)&g_attn[(size_t)(m0 + row) * E_ + kc + c];
            float4 w4 = *(const float4*)&Wo[(size_t)(e0 + row) * E_ + kc + c];
            a_s[row * PW + c + 0] = __uint_as_float(f2tf(a4.x));
            a_s[row * PW + c + 1] = __uint_as_float(f2tf(a4.y));
            a_s[row * PW + c + 2] = __uint_as_float(f2tf(a4.z));
            a_s[row * PW + c + 3] = __uint_as_float(f2tf(a4.w));
            w_s[row * PW + c + 0] = __uint_as_float(f2tf(w4.x));
            w_s[row * PW + c + 1] = __uint_as_float(f2tf(w4.y));
            w_s[row * PW + c + 2] = __uint_as_float(f2tf(w4.z));
            w_s[row * PW + c + 3] = __uint_as_float(f2tf(w4.w));
        }
        __syncthreads();

        #pragma unroll
        for (int ks = 0; ks < 8; ks++) {
            unsigned af[4][4];
            #pragma unroll
            for (int mt = 0; mt < 4; mt++) {
                int r = wm + mt * 16 + grp;
                af[mt][0] = au[r * PW + ks * 8 + qd];
                af[mt][1] = au[(r + 8) * PW + ks * 8 + qd];
                af[mt][2] = au[r * PW + ks * 8 + qd + 4];
                af[mt][3] = au[(r + 8) * PW + ks * 8 + qd + 4];
            }
            unsigned bf[4][2];
            #pragma unroll
            for (int nt = 0; nt < 4; nt++) {
                int nrow = wn + nt * 8 + grp;
                bf[nt][0] = wu[nrow * PW + ks * 8 + qd];
                bf[nt][1] = wu[nrow * PW + ks * 8 + qd + 4];
            }
            #pragma unroll
            for (int mt = 0; mt < 4; mt++)
                #pragma unroll
                for (int nt = 0; nt < 4; nt++)
                    mma_tf32(acc[mt][nt], af[mt][0], af[mt][1], af[mt][2], af[mt][3],
                             bf[nt][0], bf[nt][1]);
        }
    }

    // epilogue
    #pragma unroll
    for (int mt = 0; mt < 4; mt++) {
        int rA = m0 + wm + mt * 16 + grp;
        int rB = rA + 8;
        #pragma unroll
        for (int nt = 0; nt < 4; nt++) {
            int col = e0 + wn + nt * 8 + 2 * qd;
            float b0 = bo[col], b1 = bo[col + 1];
            float2 olo = make_float2(acc[mt][nt][0] + b0, acc[mt][nt][1] + b1);
            float2 ohi = make_float2(acc[mt][nt][2] + b0, acc[mt][nt][3] + b1);
            *(float2*)&out[(size_t)rA * E_ + col] = olo;
            *(float2*)&out[(size_t)rB * E_ + col] = ohi;
        }
    }
}

// ---------------------------------------------------------------------------
extern "C" void kernel_launch(void* const* d_in, const int* in_sizes, int n_in,
                              void* d_out, int out_size)
{
    const float* x    = (const float*)d_in[0];
    const float* Wq   = (const float*)d_in[1];
    const float* bq   = (const float*)d_in[2];
    const float* Wk   = (const float*)d_in[3];
    const float* bk   = (const float*)d_in[4];
    const float* Wv   = (const float*)d_in[5];
    const float* bv   = (const float*)d_in[6];
    const float* Erel = (const float*)d_in[7];
    const float* Wo   = (const float*)d_in[8];
    const float* bo   = (const float*)d_in[9];
    float* out = (float*)d_out;

    const int attn_smem = (KT + KT + QT + QT + 192) * PW * (int)sizeof(float); // 156,672 B
    const int proj_smem = 2 * 128 * PW * (int)sizeof(float);                   // 69,632 B
    cudaFuncSetAttribute(sa_attn_mma,
                         cudaFuncAttributeMaxDynamicSharedMemorySize, attn_smem);
    cudaFuncSetAttribute(sa_outproj_mma,
                         cudaFuncAttributeMaxDynamicSharedMemorySize, proj_smem);

    sa_qkv_kernel<<<(N_ * L_ * H_) / 64, 256>>>(x, Wq, bq, Wk, bk, Wv, bv);
    sa_attn_mma<<<dim3(L_ / QT, H_, N_), 256, attn_smem>>>(Erel);
    sa_outproj_mma<<<dim3(E_ / 128, (N_ * L_) / 128), 256, proj_smem>>>(Wo, bo, out);
}